// round 6
// baseline (speedup 1.0000x reference)
#include <cuda_runtime.h>
#include <math.h>

#define HDC_D      10000
#define HDC_T      2048
#define HDC_LEVELS 100
#define TPB        128     // 4 warps share one tile; each warp = distinct time-chunk
#define WCOLS      128     // columns per warp tile (4 per thread)
#define EFFC       126     // effective output columns per block (2-col halo)
#define NBD        80      // ceil(10000 / 126)
#define NT         32      // time-chunks (4 per block in y)
#define MTOT       2046    // T - 2 product terms
#define MCHUNK     64      // terms per chunk
#define SIDX_N     258     // idx rows staged per block (4*64 + 2)

// partial sums per time-chunk; disjoint plain stores -> deterministic
__device__ float g_partial[NT * HDC_D];

typedef unsigned long long ull;

// ---------- packed f32x2 helpers (Blackwell) ----------
__device__ __forceinline__ ull pk2(float lo, float hi) {
    ull r; asm("mov.b64 %0, {%1, %2};" : "=l"(r) : "f"(lo), "f"(hi)); return r;
}
__device__ __forceinline__ void up2(ull v, float& lo, float& hi) {
    asm("mov.b64 {%0, %1}, %2;" : "=f"(lo), "=f"(hi) : "l"(v));
}
__device__ __forceinline__ ull fma2(ull a, ull b, ull c) {
    ull d; asm("fma.rn.f32x2 %0, %1, %2, %3;" : "=l"(d) : "l"(a), "l"(b), "l"(c)); return d;
}
__device__ __forceinline__ ull mul2(ull a, ull b) {
    ull d; asm("mul.rn.f32x2 %0, %1, %2;" : "=l"(d) : "l"(a), "l"(b)); return d;
}

// dynamic smem: float tile[100*128] (51200B) + ushort4 sidx[258] (2064B)
#define TILE_FLOATS (HDC_LEVELS * WCOLS)
#define SMEM_BYTES  (TILE_FLOATS * 4 + SIDX_N * 8)

__global__ void __launch_bounds__(TPB)
hv_kernel(const float* __restrict__ inp,
          const float* __restrict__ keys,
          const float* __restrict__ level) {
    extern __shared__ float smem[];
    float*   tile = smem;
    ushort4* sidx = reinterpret_cast<ushort4*>(smem + TILE_FLOATS);

    const int tid  = threadIdx.x;
    const int warp = tid >> 5;
    const int lane = tid & 31;

    // --- fused idx prep: this block's t-slice -> shared, pre-scaled by 128 ---
    const int t_base = 4 * MCHUNK * blockIdx.y;
    const int scnt   = min(SIDX_N, HDC_T - t_base);
    for (int i = tid; i < scnt; i += TPB) {
        float4 v = reinterpret_cast<const float4*>(inp)[t_base + i];
        // jnp.round = round half to even -> __float2int_rn
        int i0 = min(max(__float2int_rn(v.x * 99.0f), 0), 99);
        int i1 = min(max(__float2int_rn(v.y * 99.0f), 0), 99);
        int i2 = min(max(__float2int_rn(v.z * 99.0f), 0), 99);
        int i3 = min(max(__float2int_rn(v.w * 99.0f), 0), 99);
        sidx[i] = make_ushort4((unsigned short)(i0 * WCOLS), (unsigned short)(i1 * WCOLS),
                               (unsigned short)(i2 * WCOLS), (unsigned short)(i3 * WCOLS));
    }

    // --- stage 100 x 128 level tile (float2, coalesced; circular in d) ---
    const int gstart = blockIdx.x * EFFC - 2;   // even
    for (int i = tid; i < HDC_LEVELS * (WCOLS / 2); i += TPB) {
        int row = i >> 6;          // / 64
        int j   = i & 63;
        int g = gstart + 2 * j;
        if (g < 0)       g += HDC_D;
        if (g >= HDC_D)  g -= HDC_D;
        *reinterpret_cast<float2*>(tile + row * WCOLS + 2 * j) =
            *reinterpret_cast<const float2*>(level + row * HDC_D + g);
    }

    // --- per-thread keys for its 4 columns (2 aligned float2 pairs) ---
    const int p0 = gstart + 4 * lane;   // even; pairs never straddle the D wrap
    int ga = p0;
    if (ga < 0)       ga += HDC_D;
    if (ga >= HDC_D)  ga -= HDC_D;
    int gb = p0 + 2;
    if (gb < 0)       gb += HDC_D;
    if (gb >= HDC_D)  gb -= HDC_D;

    ull Klo[4], Khi[4];
    #pragma unroll
    for (int c = 0; c < 4; c++) {
        float2 A = *reinterpret_cast<const float2*>(keys + c * HDC_D + ga);
        float2 B = *reinterpret_cast<const float2*>(keys + c * HDC_D + gb);
        Klo[c] = pk2(A.x, A.y);
        Khi[c] = pk2(B.x, B.y);
    }
    __syncthreads();

    const int ct    = blockIdx.y * 4 + warp;
    const int m0    = ct * MCHUNK;
    const int iters = min(MCHUNK, MTOT - m0) + 2;
    const int soff  = warp * MCHUNK;            // m0 - t_base
    const float* wt = tile + 4 * lane;

    ull h1lo = 0, h1hi = 0, h2lo = 0, h2hi = 0, acclo = 0, acchi = 0;

    #pragma unroll 4
    for (int j = 0; j < iters; j++) {
        ushort4 u = sidx[soff + j];             // broadcast LDS.64
        float4 L0 = *reinterpret_cast<const float4*>(wt + u.x);
        float4 L1 = *reinterpret_cast<const float4*>(wt + u.y);
        float4 L2 = *reinterpret_cast<const float4*>(wt + u.z);
        float4 L3 = *reinterpret_cast<const float4*>(wt + u.w);

        ull Hlo = fma2(Klo[0], pk2(L0.x, L0.y),
                  fma2(Klo[1], pk2(L1.x, L1.y),
                  fma2(Klo[2], pk2(L2.x, L2.y),
                  mul2(Klo[3], pk2(L3.x, L3.y)))));
        ull Hhi = fma2(Khi[0], pk2(L0.z, L0.w),
                  fma2(Khi[1], pk2(L1.z, L1.w),
                  fma2(Khi[2], pk2(L2.z, L2.w),
                  mul2(Khi[3], pk2(L3.z, L3.w)))));

        // a = hv[t-2] at d-2: cols (c0,c1) <- lane-1's (c2,c3); (c2,c3) <- own (c0,c1)
        ull a_lo = __shfl_up_sync(0xffffffffu, h2hi, 1);
        ull a_hi = h2lo;
        // b = hv[t-1] at d-1: c0 <- lane-1's c3; c1,c2,c3 <- own c0,c1,c2
        float h1hx, h1hy, h1lx, h1ly;
        up2(h1hi, h1hx, h1hy);
        up2(h1lo, h1lx, h1ly);
        float bl0 = __shfl_up_sync(0xffffffffu, h1hy, 1);
        ull b_lo = pk2(bl0, h1lx);
        ull b_hi = pk2(h1ly, h1hx);

        acclo = fma2(mul2(a_lo, b_lo), Hlo, acclo);  // zero history -> first 2 iters add 0
        acchi = fma2(mul2(a_hi, b_hi), Hhi, acchi);

        h2lo = h1lo; h2hi = h1hi;
        h1lo = Hlo;  h1hi = Hhi;
    }

    // outputs: block owns cols [126*bx, 126*bx+126); lane0 cols 0,1 are halo.
    // p0 is even but NOT always 16B-aligned -> use two float2 (8B) stores.
    float alx, aly, ahx, ahy;
    up2(acclo, alx, aly);
    up2(acchi, ahx, ahy);
    float* dst = &g_partial[ct * HDC_D];
    if (lane == 0) {
        *reinterpret_cast<float2*>(dst + p0 + 2) = make_float2(ahx, ahy);
    } else if (p0 < HDC_D) {
        *reinterpret_cast<float2*>(dst + p0)     = make_float2(alx, aly);
        *reinterpret_cast<float2*>(dst + p0 + 2) = make_float2(ahx, ahy);
    }
}

__global__ void epilogue_kernel(const float* __restrict__ feat,
                                const float* __restrict__ W3,
                                const float* __restrict__ b3,
                                const float* __restrict__ W6,
                                const float* __restrict__ b6,
                                float* __restrict__ out) {
    int d = blockIdx.x * blockDim.x + threadIdx.x;
    if (d >= HDC_D) return;

    // ---- issue ALL independent loads first (maximize MLP) ----
    float pr[NT];
    #pragma unroll
    for (int c = 0; c < NT; c++) pr[c] = g_partial[c * HDC_D + d];

    float w3v[8][3], b3v[8];
    #pragma unroll
    for (int k = 0; k < 8; k++) {
        const float* w = W3 + (k * HDC_D + d) * 3;
        w3v[k][0] = w[0]; w3v[k][1] = w[1]; w3v[k][2] = w[2];
        b3v[k] = b3[k * HDC_D + d];
    }
    float w6v[6];
    #pragma unroll
    for (int i = 0; i < 6; i++) w6v[i] = W6[d * 6 + i];
    float b6v = b6[d];

    float fv[30];
    #pragma unroll
    for (int i = 0; i < 30; i++) fv[i] = feat[i];

    // ---- compute ----
    float s = 0.0f;
    #pragma unroll
    for (int c = 0; c < NT; c++) s += pr[c];

    const int S[8] = {0, 9, 12, 15, 18, 21, 24, 27};
    float h[8];
    #pragma unroll
    for (int k = 0; k < 8; k++) {
        float p = w3v[k][0] * fv[S[k]] + w3v[k][1] * fv[S[k] + 1] + w3v[k][2] * fv[S[k] + 2];
        h[k] = cosf(p + b3v[k]) * sinf(p);
    }

    float p6 = 0.0f;
    #pragma unroll
    for (int i = 0; i < 6; i++) p6 += w6v[i] * fv[3 + i];
    float h6 = cosf(p6 + b6v) * sinf(p6);

    // match reference multiply order exactly
    float o = s * h[0];
    o *= (h6 + h[7]);
    o *= (h[1] + h[2] + h[3]);
    o *= (h[4] + h[5] + h[6]);
    out[d] = (o > 0.0f) ? 1.0f : -1.0f;
}

extern "C" void kernel_launch(void* const* d_in, const int* in_sizes, int n_in,
                              void* d_out, int out_size) {
    const float* inp   = (const float*)d_in[0];
    const float* feat  = (const float*)d_in[1];
    const float* keys  = (const float*)d_in[2];
    const float* level = (const float*)d_in[3];
    const float* W3    = (const float*)d_in[4];
    const float* b3    = (const float*)d_in[5];
    const float* W6    = (const float*)d_in[6];
    const float* b6    = (const float*)d_in[7];
    float* out = (float*)d_out;

    cudaFuncSetAttribute(hv_kernel, cudaFuncAttributeMaxDynamicSharedMemorySize,
                         SMEM_BYTES);

    dim3 grid(NBD, NT / 4);
    hv_kernel<<<grid, TPB, SMEM_BYTES>>>(inp, keys, level);
    epilogue_kernel<<<(HDC_D + 255) / 256, 256>>>(feat, W3, b3, W6, b6, out);
}

// round 8
// speedup vs baseline: 1.2754x; 1.2754x over previous
#include <cuda_runtime.h>
#include <math.h>

#define HDC_D      10000
#define HDC_T      2048
#define HDC_LEVELS 100
#define TPB        256     // 8 warps share one tile; each warp = distinct time-chunk
#define WCOLS      128     // columns per block tile (4 per thread)
#define EFFC       126     // effective output columns per block (2-col halo)
#define NBD        80      // ceil(10000 / 126)
#define NTY        5       // grid.y
#define NT         40      // time-chunks (8 per block)
#define MTOT       2046    // T - 2 product terms
#define MCHUNK     52      // terms per chunk (52*40 = 2080 >= 2046)
#define SIDX_N     (8 * MCHUNK + 2)   // 418 idx rows staged per block

// partial sums per time-chunk; disjoint plain stores -> deterministic
__device__ float g_partial[NT * HDC_D];

typedef unsigned long long ull;

// ---------- packed f32x2 helpers (Blackwell) ----------
__device__ __forceinline__ ull pk2(float lo, float hi) {
    ull r; asm("mov.b64 %0, {%1, %2};" : "=l"(r) : "f"(lo), "f"(hi)); return r;
}
__device__ __forceinline__ void up2(ull v, float& lo, float& hi) {
    asm("mov.b64 {%0, %1}, %2;" : "=f"(lo), "=f"(hi) : "l"(v));
}
__device__ __forceinline__ ull fma2(ull a, ull b, ull c) {
    ull d; asm("fma.rn.f32x2 %0, %1, %2, %3;" : "=l"(d) : "l"(a), "l"(b), "l"(c)); return d;
}
__device__ __forceinline__ ull mul2(ull a, ull b) {
    ull d; asm("mul.rn.f32x2 %0, %1, %2;" : "=l"(d) : "l"(a), "l"(b)); return d;
}

// dynamic smem: float tile[100*128] (51200B) + ushort4 sidx[418] (3344B)
#define TILE_FLOATS (HDC_LEVELS * WCOLS)
#define SMEM_BYTES  (TILE_FLOATS * 4 + SIDX_N * 8)

__global__ void __launch_bounds__(TPB)
hv_kernel(const float* __restrict__ inp,
          const float* __restrict__ keys,
          const float* __restrict__ level) {
    extern __shared__ float smem[];
    float*   tile = smem;
    ushort4* sidx = reinterpret_cast<ushort4*>(smem + TILE_FLOATS);

    const int tid  = threadIdx.x;
    const int warp = tid >> 5;
    const int lane = tid & 31;

    // --- fused idx prep: this block's t-slice -> shared, pre-scaled by 128 ---
    const int t_base = 8 * MCHUNK * blockIdx.y;
    const int scnt   = min(SIDX_N, HDC_T - t_base);
    for (int i = tid; i < scnt; i += TPB) {
        float4 v = reinterpret_cast<const float4*>(inp)[t_base + i];
        // jnp.round = round half to even -> __float2int_rn
        int i0 = min(max(__float2int_rn(v.x * 99.0f), 0), 99);
        int i1 = min(max(__float2int_rn(v.y * 99.0f), 0), 99);
        int i2 = min(max(__float2int_rn(v.z * 99.0f), 0), 99);
        int i3 = min(max(__float2int_rn(v.w * 99.0f), 0), 99);
        sidx[i] = make_ushort4((unsigned short)(i0 * WCOLS), (unsigned short)(i1 * WCOLS),
                               (unsigned short)(i2 * WCOLS), (unsigned short)(i3 * WCOLS));
    }

    // --- stage 100 x 128 level tile (float2, coalesced; circular in d) ---
    const int gstart = blockIdx.x * EFFC - 2;   // even
    for (int i = tid; i < HDC_LEVELS * (WCOLS / 2); i += TPB) {
        int row = i >> 6;          // / 64
        int j   = i & 63;
        int g = gstart + 2 * j;
        if (g < 0)       g += HDC_D;
        if (g >= HDC_D)  g -= HDC_D;
        *reinterpret_cast<float2*>(tile + row * WCOLS + 2 * j) =
            *reinterpret_cast<const float2*>(level + row * HDC_D + g);
    }

    // --- per-thread keys for its 4 columns (2 aligned float2 pairs) ---
    const int p0 = gstart + 4 * lane;   // even; pairs never straddle the D wrap
    int ga = p0;
    if (ga < 0)       ga += HDC_D;
    if (ga >= HDC_D)  ga -= HDC_D;
    int gb = p0 + 2;
    if (gb < 0)       gb += HDC_D;
    if (gb >= HDC_D)  gb -= HDC_D;

    ull Klo[4], Khi[4];
    #pragma unroll
    for (int c = 0; c < 4; c++) {
        float2 A = *reinterpret_cast<const float2*>(keys + c * HDC_D + ga);
        float2 B = *reinterpret_cast<const float2*>(keys + c * HDC_D + gb);
        Klo[c] = pk2(A.x, A.y);
        Khi[c] = pk2(B.x, B.y);
    }
    __syncthreads();

    const int ct    = blockIdx.y * 8 + warp;
    const int m0    = ct * MCHUNK;
    const int iters = min(MCHUNK, MTOT - m0) + 2;
    const int soff  = warp * MCHUNK;            // m0 - t_base
    const float* wt = tile + 4 * lane;

    ull h1lo = 0, h1hi = 0, h2lo = 0, h2hi = 0, acclo = 0, acchi = 0;

    #pragma unroll 4
    for (int j = 0; j < iters; j++) {
        ushort4 u = sidx[soff + j];             // broadcast LDS.64
        float4 L0 = *reinterpret_cast<const float4*>(wt + u.x);
        float4 L1 = *reinterpret_cast<const float4*>(wt + u.y);
        float4 L2 = *reinterpret_cast<const float4*>(wt + u.z);
        float4 L3 = *reinterpret_cast<const float4*>(wt + u.w);

        ull Hlo = fma2(Klo[0], pk2(L0.x, L0.y),
                  fma2(Klo[1], pk2(L1.x, L1.y),
                  fma2(Klo[2], pk2(L2.x, L2.y),
                  mul2(Klo[3], pk2(L3.x, L3.y)))));
        ull Hhi = fma2(Khi[0], pk2(L0.z, L0.w),
                  fma2(Khi[1], pk2(L1.z, L1.w),
                  fma2(Khi[2], pk2(L2.z, L2.w),
                  mul2(Khi[3], pk2(L3.z, L3.w)))));

        // a = hv[t-2] at d-2: cols (c0,c1) <- lane-1's (c2,c3); (c2,c3) <- own (c0,c1)
        ull a_lo = __shfl_up_sync(0xffffffffu, h2hi, 1);
        ull a_hi = h2lo;
        // b = hv[t-1] at d-1: c0 <- lane-1's c3; c1,c2,c3 <- own c0,c1,c2
        float h1hx, h1hy, h1lx, h1ly;
        up2(h1hi, h1hx, h1hy);
        up2(h1lo, h1lx, h1ly);
        float bl0 = __shfl_up_sync(0xffffffffu, h1hy, 1);
        ull b_lo = pk2(bl0, h1lx);
        ull b_hi = pk2(h1ly, h1hx);

        acclo = fma2(mul2(a_lo, b_lo), Hlo, acclo);  // zero history -> first 2 iters add 0
        acchi = fma2(mul2(a_hi, b_hi), Hhi, acchi);

        h2lo = h1lo; h2hi = h1hi;
        h1lo = Hlo;  h1hi = Hhi;
    }

    // outputs: block owns cols [126*bx, 126*bx+126); lane0 cols 0,1 are halo.
    // p0 is even but not always 16B-aligned -> two float2 (8B) stores.
    float alx, aly, ahx, ahy;
    up2(acclo, alx, aly);
    up2(acchi, ahx, ahy);
    float* dst = &g_partial[ct * HDC_D];
    if (lane == 0) {
        *reinterpret_cast<float2*>(dst + p0 + 2) = make_float2(ahx, ahy);
    } else if (p0 < HDC_D) {
        *reinterpret_cast<float2*>(dst + p0)     = make_float2(alx, aly);
        *reinterpret_cast<float2*>(dst + p0 + 2) = make_float2(ahx, ahy);
    }
}

__global__ void epilogue_kernel(const float* __restrict__ feat,
                                const float* __restrict__ W3,
                                const float* __restrict__ b3,
                                const float* __restrict__ W6,
                                const float* __restrict__ b6,
                                float* __restrict__ out) {
    int d = blockIdx.x * blockDim.x + threadIdx.x;
    if (d >= HDC_D) return;

    // ---- issue ALL independent loads first (maximize MLP) ----
    float pr[NT];
    #pragma unroll
    for (int c = 0; c < NT; c++) pr[c] = g_partial[c * HDC_D + d];

    float w3v[8][3], b3v[8];
    #pragma unroll
    for (int k = 0; k < 8; k++) {
        const float* w = W3 + (k * HDC_D + d) * 3;
        w3v[k][0] = w[0]; w3v[k][1] = w[1]; w3v[k][2] = w[2];
        b3v[k] = b3[k * HDC_D + d];
    }
    float w6v[6];
    #pragma unroll
    for (int i = 0; i < 6; i++) w6v[i] = W6[d * 6 + i];
    float b6v = b6[d];

    float fv[30];
    #pragma unroll
    for (int i = 0; i < 30; i++) fv[i] = feat[i];

    // ---- compute ----
    float s = 0.0f;
    #pragma unroll
    for (int c = 0; c < NT; c++) s += pr[c];

    const int S[8] = {0, 9, 12, 15, 18, 21, 24, 27};
    float h[8];
    #pragma unroll
    for (int k = 0; k < 8; k++) {
        float p = w3v[k][0] * fv[S[k]] + w3v[k][1] * fv[S[k] + 1] + w3v[k][2] * fv[S[k] + 2];
        h[k] = cosf(p + b3v[k]) * sinf(p);
    }

    float p6 = 0.0f;
    #pragma unroll
    for (int i = 0; i < 6; i++) p6 += w6v[i] * fv[3 + i];
    float h6 = cosf(p6 + b6v) * sinf(p6);

    // match reference multiply order exactly
    float o = s * h[0];
    o *= (h6 + h[7]);
    o *= (h[1] + h[2] + h[3]);
    o *= (h[4] + h[5] + h[6]);
    out[d] = (o > 0.0f) ? 1.0f : -1.0f;
}

extern "C" void kernel_launch(void* const* d_in, const int* in_sizes, int n_in,
                              void* d_out, int out_size) {
    const float* inp   = (const float*)d_in[0];
    const float* feat  = (const float*)d_in[1];
    const float* keys  = (const float*)d_in[2];
    const float* level = (const float*)d_in[3];
    const float* W3    = (const float*)d_in[4];
    const float* b3    = (const float*)d_in[5];
    const float* W6    = (const float*)d_in[6];
    const float* b6    = (const float*)d_in[7];
    float* out = (float*)d_out;

    cudaFuncSetAttribute(hv_kernel, cudaFuncAttributeMaxDynamicSharedMemorySize,
                         SMEM_BYTES);

    dim3 grid(NBD, NTY);
    hv_kernel<<<grid, TPB, SMEM_BYTES>>>(inp, keys, level);
    epilogue_kernel<<<(HDC_D + 63) / 64, 64>>>(feat, W3, b3, W6, b6, out);
}

// round 9
// speedup vs baseline: 1.3452x; 1.0548x over previous
#include <cuda_runtime.h>
#include <math.h>

#define HDC_D      10000
#define HDC_T      2048
#define HDC_LEVELS 100
#define TPB        256     // 8 warps share one tile; each warp = distinct time-chunk
#define WCOLS      128     // columns per block tile (4 per thread)
#define EFFC       126     // effective output columns per block (2-col halo)
#define NBD        80      // ceil(10000 / 126)
#define NTY        5       // grid.y
#define NT         40      // time-chunks (8 per block)
#define MTOT       2046    // T - 2 product terms
#define MCHUNK     52      // terms per chunk (52*40 = 2080 >= 2046)
#define SIDX_N     (8 * MCHUNK + 2)   // 418 idx rows staged per block

// partial sums, TRANSPOSED layout [d][NT] so the epilogue reads float4s
__device__ float g_partial[HDC_D * NT];

typedef unsigned long long ull;
typedef unsigned int uint;

// ---------- packed f32x2 helpers (Blackwell) ----------
__device__ __forceinline__ ull pk2(float lo, float hi) {
    ull r; asm("mov.b64 %0, {%1, %2};" : "=l"(r) : "f"(lo), "f"(hi)); return r;
}
__device__ __forceinline__ void up2(ull v, float& lo, float& hi) {
    asm("mov.b64 {%0, %1}, %2;" : "=f"(lo), "=f"(hi) : "l"(v));
}
__device__ __forceinline__ ull fma2(ull a, ull b, ull c) {
    ull d; asm("fma.rn.f32x2 %0, %1, %2, %3;" : "=l"(d) : "l"(a), "l"(b), "l"(c)); return d;
}
__device__ __forceinline__ ull mul2(ull a, ull b) {
    ull d; asm("mul.rn.f32x2 %0, %1, %2;" : "=l"(d) : "l"(a), "l"(b)); return d;
}

__device__ __forceinline__ int wrapD(int g) {
    if (g < 0)       g += HDC_D;
    if (g >= HDC_D)  g -= HDC_D;
    return g;
}

__global__ void __launch_bounds__(TPB)
hv_kernel(const float* __restrict__ inp,
          const float* __restrict__ keys,
          const float* __restrict__ level) {
    // sign tile: byte = 1 if level < 0 else 0.  12.8 KB + 3.3 KB static smem.
    __shared__ unsigned char tile8[HDC_LEVELS * WCOLS];
    __shared__ ushort4 sidx[SIDX_N];

    const int tid  = threadIdx.x;
    const int warp = tid >> 5;
    const int lane = tid & 31;

    // --- fused idx prep: this block's t-slice -> shared, pre-scaled by 128 B ---
    const int t_base = 8 * MCHUNK * blockIdx.y;
    const int scnt   = min(SIDX_N, HDC_T - t_base);
    for (int i = tid; i < scnt; i += TPB) {
        float4 v = reinterpret_cast<const float4*>(inp)[t_base + i];
        // jnp.round = round half to even -> __float2int_rn
        int i0 = min(max(__float2int_rn(v.x * 99.0f), 0), 99);
        int i1 = min(max(__float2int_rn(v.y * 99.0f), 0), 99);
        int i2 = min(max(__float2int_rn(v.z * 99.0f), 0), 99);
        int i3 = min(max(__float2int_rn(v.w * 99.0f), 0), 99);
        sidx[i] = make_ushort4((unsigned short)(i0 * WCOLS), (unsigned short)(i1 * WCOLS),
                               (unsigned short)(i2 * WCOLS), (unsigned short)(i3 * WCOLS));
    }

    // --- stage 100 x 128 sign-byte tile (4 cols per thread-iter, STS.32) ---
    const int gstart = blockIdx.x * EFFC - 2;   // even
    for (int i = tid; i < HDC_LEVELS * (WCOLS / 4); i += TPB) {
        int row = i >> 5;          // / 32
        int q   = i & 31;          // quad of 4 columns
        int ga = wrapD(gstart + 4 * q);
        int gb = wrapD(gstart + 4 * q + 2);
        float2 A = *reinterpret_cast<const float2*>(level + row * HDC_D + ga);
        float2 B = *reinterpret_cast<const float2*>(level + row * HDC_D + gb);
        uint w =  (__float_as_uint(A.x) >> 31)
               | ((__float_as_uint(A.y) >> 31) << 8)
               | ((__float_as_uint(B.x) >> 31) << 16)
               | ((__float_as_uint(B.y) >> 31) << 24);
        *reinterpret_cast<uint*>(tile8 + row * WCOLS + 4 * q) = w;
    }

    // --- per-thread packed key sign bytes, one word per channel ---
    const int p0 = gstart + 4 * lane;   // even
    uint K[4];
    #pragma unroll
    for (int c = 0; c < 4; c++) {
        uint w = 0;
        #pragma unroll
        for (int j = 0; j < 4; j++) {
            int col = wrapD(p0 + j);
            w |= (__float_as_uint(keys[c * HDC_D + col]) >> 31) << (8 * j);
        }
        K[c] = w;
    }
    __syncthreads();

    const int ct    = blockIdx.y * 8 + warp;
    const int m0    = ct * MCHUNK;
    const int iters = min(MCHUNK, MTOT - m0) + 2;
    const int soff  = warp * MCHUNK;            // m0 - t_base
    const unsigned char* tp = tile8 + 4 * lane;

    const ull Cm2 = pk2(-2.0f, -2.0f);
    const ull C4  = pk2( 4.0f,  4.0f);

    ull h1lo = 0, h1hi = 0, h2lo = 0, h2hi = 0, acclo = 0, acchi = 0;

    #pragma unroll 4
    for (int j = 0; j < iters; j++) {
        ushort4 u = sidx[soff + j];             // broadcast LDS.64
        uint R0 = *reinterpret_cast<const uint*>(tp + u.x);
        uint R1 = *reinterpret_cast<const uint*>(tp + u.y);
        uint R2 = *reinterpret_cast<const uint*>(tp + u.z);
        uint R3 = *reinterpret_cast<const uint*>(tp + u.w);

        // per-byte count of negative products; bytes <= 4, no carry
        uint P = (R0 ^ K[0]) + (R1 ^ K[1]) + (R2 ^ K[2]) + (R3 ^ K[3]);
        int s0 = __dp4a((int)P, 0x00000001, 0);
        int s1 = __dp4a((int)P, 0x00000100, 0);
        int s2 = __dp4a((int)P, 0x00010000, 0);
        int s3 = __dp4a((int)P, 0x01000000, 0);

        // hv = 4 - 2*s  (exact)
        ull Hlo = fma2(pk2((float)s0, (float)s1), Cm2, C4);
        ull Hhi = fma2(pk2((float)s2, (float)s3), Cm2, C4);

        // a = hv[t-2] at d-2: cols (c0,c1) <- lane-1's (c2,c3); (c2,c3) <- own (c0,c1)
        ull a_lo = __shfl_up_sync(0xffffffffu, h2hi, 1);
        ull a_hi = h2lo;
        // b = hv[t-1] at d-1: c0 <- lane-1's c3; c1,c2,c3 <- own c0,c1,c2
        float h1hx, h1hy, h1lx, h1ly;
        up2(h1hi, h1hx, h1hy);
        up2(h1lo, h1lx, h1ly);
        float bl0 = __shfl_up_sync(0xffffffffu, h1hy, 1);
        ull b_lo = pk2(bl0, h1lx);
        ull b_hi = pk2(h1ly, h1hx);

        acclo = fma2(mul2(a_lo, b_lo), Hlo, acclo);  // zero history -> first 2 iters add 0
        acchi = fma2(mul2(a_hi, b_hi), Hhi, acchi);

        h2lo = h1lo; h2hi = h1hi;
        h1lo = Hlo;  h1hi = Hhi;
    }

    // transposed scatter: g_partial[d][ct]. lane0 owns only its hi pair.
    float alx, aly, ahx, ahy;
    up2(acclo, alx, aly);
    up2(acchi, ahx, ahy);
    if (lane == 0) {
        g_partial[(p0 + 2) * NT + ct] = ahx;
        g_partial[(p0 + 3) * NT + ct] = ahy;
    } else if (p0 < HDC_D) {
        g_partial[(p0    ) * NT + ct] = alx;
        g_partial[(p0 + 1) * NT + ct] = aly;
        g_partial[(p0 + 2) * NT + ct] = ahx;
        g_partial[(p0 + 3) * NT + ct] = ahy;
    }
}

__global__ void epilogue_kernel(const float* __restrict__ feat,
                                const float* __restrict__ W3,
                                const float* __restrict__ b3,
                                const float* __restrict__ W6,
                                const float* __restrict__ b6,
                                float* __restrict__ out) {
    int d = blockIdx.x * blockDim.x + threadIdx.x;
    if (d >= HDC_D) return;

    // ---- issue ALL independent loads first (maximize MLP) ----
    const float4* pp = reinterpret_cast<const float4*>(g_partial + d * NT);
    float4 pr[NT / 4];
    #pragma unroll
    for (int c = 0; c < NT / 4; c++) pr[c] = pp[c];

    float w3v[8][3], b3v[8];
    #pragma unroll
    for (int k = 0; k < 8; k++) {
        const float* w = W3 + (k * HDC_D + d) * 3;
        w3v[k][0] = w[0]; w3v[k][1] = w[1]; w3v[k][2] = w[2];
        b3v[k] = b3[k * HDC_D + d];
    }
    float w6v[6];
    #pragma unroll
    for (int i = 0; i < 6; i++) w6v[i] = W6[d * 6 + i];
    float b6v = b6[d];

    float fv[30];
    #pragma unroll
    for (int i = 0; i < 30; i++) fv[i] = feat[i];

    // ---- compute ----
    float s = 0.0f;
    #pragma unroll
    for (int c = 0; c < NT / 4; c++) s += (pr[c].x + pr[c].y) + (pr[c].z + pr[c].w);

    const int S[8] = {0, 9, 12, 15, 18, 21, 24, 27};
    float h[8];
    #pragma unroll
    for (int k = 0; k < 8; k++) {
        float p = w3v[k][0] * fv[S[k]] + w3v[k][1] * fv[S[k] + 1] + w3v[k][2] * fv[S[k] + 2];
        h[k] = cosf(p + b3v[k]) * sinf(p);
    }

    float p6 = 0.0f;
    #pragma unroll
    for (int i = 0; i < 6; i++) p6 += w6v[i] * fv[3 + i];
    float h6 = cosf(p6 + b6v) * sinf(p6);

    // match reference multiply order exactly
    float o = s * h[0];
    o *= (h6 + h[7]);
    o *= (h[1] + h[2] + h[3]);
    o *= (h[4] + h[5] + h[6]);
    out[d] = (o > 0.0f) ? 1.0f : -1.0f;
}

extern "C" void kernel_launch(void* const* d_in, const int* in_sizes, int n_in,
                              void* d_out, int out_size) {
    const float* inp   = (const float*)d_in[0];
    const float* feat  = (const float*)d_in[1];
    const float* keys  = (const float*)d_in[2];
    const float* level = (const float*)d_in[3];
    const float* W3    = (const float*)d_in[4];
    const float* b3    = (const float*)d_in[5];
    const float* W6    = (const float*)d_in[6];
    const float* b6    = (const float*)d_in[7];
    float* out = (float*)d_out;

    dim3 grid(NBD, NTY);
    hv_kernel<<<grid, TPB>>>(inp, keys, level);
    epilogue_kernel<<<(HDC_D + 127) / 128, 128>>>(feat, W3, b3, W6, b6, out);
}